// round 3
// baseline (speedup 1.0000x reference)
#include <cuda_runtime.h>
#include <math.h>

// Problem constants (fixed by the dataset)
#define N_NODES 20000
#define CIN     128
#define CH      640
#define COUT    2
#define E_IN    320000
#define EA_MAX  (E_IN + N_NODES)   // edges + self loops = 340000
#define NEG_SLOPE 0.2f

// ---------------- scratch (device globals; referenced ONLY from device code) ----
__device__ float g_h [N_NODES * CH];   // layer input/output activations
__device__ float g_hw[N_NODES * CH];   // hW = h @ W
__device__ float g_as[N_NODES];        // per-node alpha_src = hW . a_src
__device__ float g_ad[N_NODES];        // per-node alpha_dst = hW . a_dst
__device__ int   g_off [N_NODES + 1];  // CSR offsets by dst
__device__ int   g_fill[N_NODES];      // degree counter / fill pointer
__device__ int   g_srcs[EA_MAX];       // src node per CSR slot
__device__ int   g_is64;               // 1 if edge_index is int64, 0 if int32

// ---------------- edge_index dtype detection ----------------
// int64 little-endian with values < 2^31: every odd 32-bit word is 0.
// int32 with values uniform in [0, 20000): odd words are ~never all zero.
__global__ void k_detect(const int* __restrict__ ei32) {
    __shared__ int nz;
    if (threadIdx.x == 0) nz = 0;
    __syncthreads();
    for (int i = threadIdx.x; i < 1024; i += blockDim.x)
        if (ei32[2 * i + 1] != 0) nz = 1;
    __syncthreads();
    if (threadIdx.x == 0) g_is64 = (nz == 0) ? 1 : 0;
}

__device__ __forceinline__ int edge_at(const void* ei, int idx) {
    return g_is64 ? (int)((const long long*)ei)[idx]
                  : ((const int*)ei)[idx];
}

// ---------------- CSR build (dst-sorted edge list) ----------------
__global__ void k_zero() {
    int i = blockIdx.x * blockDim.x + threadIdx.x;
    if (i < N_NODES) g_fill[i] = 0;
}

__global__ void k_count(const void* __restrict__ ei, int E, int EA) {
    int j = blockIdx.x * blockDim.x + threadIdx.x;
    if (j >= EA) return;
    int dst = (j < E) ? edge_at(ei, E + j) : (j - E);
    if (dst < 0 || dst >= N_NODES) return;  // defensive
    atomicAdd(&g_fill[dst], 1);
}

__global__ void k_scan() {   // exclusive scan of g_fill -> g_off, single block of 1024
    __shared__ int part[1024];
    const int n = N_NODES;
    int t = threadIdx.x;
    const int chunk = (n + 1023) / 1024;
    int base = t * chunk;
    int s = 0;
    for (int i = 0; i < chunk; i++) {
        int idx = base + i;
        if (idx < n) s += g_fill[idx];
    }
    part[t] = s;
    __syncthreads();
    for (int o = 1; o < 1024; o <<= 1) {
        int v = (t >= o) ? part[t - o] : 0;
        __syncthreads();
        part[t] += v;
        __syncthreads();
    }
    int run = (t == 0) ? 0 : part[t - 1];
    for (int i = 0; i < chunk; i++) {
        int idx = base + i;
        if (idx < n) { int d = g_fill[idx]; g_off[idx] = run; run += d; }
    }
    if (t == 1023) g_off[n] = part[1023];
}

__global__ void k_copy() {
    int i = blockIdx.x * blockDim.x + threadIdx.x;
    if (i < N_NODES) g_fill[i] = g_off[i];
}

__global__ void k_fill(const void* __restrict__ ei, int E, int EA) {
    int j = blockIdx.x * blockDim.x + threadIdx.x;
    if (j >= EA) return;
    int src = (j < E) ? edge_at(ei, j)     : (j - E);
    int dst = (j < E) ? edge_at(ei, E + j) : (j - E);
    if (dst < 0 || dst >= N_NODES) return;  // defensive
    if (src < 0 || src >= N_NODES) src = 0; // defensive
    int pos = atomicAdd(&g_fill[dst], 1);
    if (pos >= 0 && pos < EA_MAX) g_srcs[pos] = src;
}

// ---------------- fp32 tiled GEMM: g_hw[M,CH] = A[M,K] @ B[K,CH] ----------------
// A is either the external x (use_ext=1) or g_h (use_ext=0).
// BM=BN=64, BK=16, 256 threads, 4x4 microtile, float4 shared loads.
__global__ __launch_bounds__(256) void gemm64(
    const float* __restrict__ Aext, int use_ext,
    const float* __restrict__ B, int M, int K)
{
    const float* A = use_ext ? Aext : (const float*)g_h;
    const int Nc = CH;
    __shared__ __align__(16) float AsT[16][68];  // [k][m], padded
    __shared__ __align__(16) float Bs [16][64];  // [k][n]
    int t  = threadIdx.x;
    int tx = t & 15, ty = t >> 4;
    int bm = blockIdx.y * 64, bn = blockIdx.x * 64;
    int lm  = t >> 2;         // 0..63  (A row within tile)
    int lk  = (t & 3) << 2;   // 0,4,8,12
    int lkb = t >> 4;         // 0..15  (B row within tile)
    int lnb = (t & 15) << 2;  // 0..60

    float acc[4][4] = {};
    for (int k0 = 0; k0 < K; k0 += 16) {
        float4 a4;
        if (bm + lm < M) a4 = *(const float4*)(A + (size_t)(bm + lm) * K + k0 + lk);
        else             a4 = make_float4(0.f, 0.f, 0.f, 0.f);
        float4 b4 = *(const float4*)(B + (size_t)(k0 + lkb) * Nc + bn + lnb);
        AsT[lk + 0][lm] = a4.x; AsT[lk + 1][lm] = a4.y;
        AsT[lk + 2][lm] = a4.z; AsT[lk + 3][lm] = a4.w;
        *(float4*)&Bs[lkb][lnb] = b4;
        __syncthreads();
#pragma unroll
        for (int kk = 0; kk < 16; kk++) {
            float4 av = *(const float4*)&AsT[kk][ty << 2];
            float4 bv = *(const float4*)&Bs [kk][tx << 2];
            float a[4] = {av.x, av.y, av.z, av.w};
            float b[4] = {bv.x, bv.y, bv.z, bv.w};
#pragma unroll
            for (int i = 0; i < 4; i++)
#pragma unroll
                for (int j = 0; j < 4; j++)
                    acc[i][j] = fmaf(a[i], b[j], acc[i][j]);
        }
        __syncthreads();
    }
#pragma unroll
    for (int i = 0; i < 4; i++) {
        int m = bm + (ty << 2) + i;
        if (m < M) {
            float4 v = make_float4(acc[i][0], acc[i][1], acc[i][2], acc[i][3]);
            *(float4*)(g_hw + (size_t)m * Nc + bn + (tx << 2)) = v;
        }
    }
}

// ---------------- per-node attention logits (warp per node, reads g_hw) -------
__global__ void k_alphas(const float* __restrict__ a_s,
                         const float* __restrict__ a_d)
{
    int gw = (blockIdx.x * blockDim.x + threadIdx.x) >> 5;
    int lane = threadIdx.x & 31;
    if (gw >= N_NODES) return;
    const float* row = g_hw + (size_t)gw * CH;
    float s = 0.f, d = 0.f;
    for (int c = lane; c < CH; c += 32) {
        float v = row[c];
        s = fmaf(v, a_s[c], s);
        d = fmaf(v, a_d[c], d);
    }
#pragma unroll
    for (int o = 16; o; o >>= 1) {
        s += __shfl_down_sync(0xffffffffu, s, o);
        d += __shfl_down_sync(0xffffffffu, d, o);
    }
    if (lane == 0) { g_as[gw] = s; g_ad[gw] = d; }
}

// ---------------- layer 5 projection + logits (warp per node, Co=2) -----------
__global__ void k_layer5(const float* __restrict__ W,
                         const float* __restrict__ a_s,
                         const float* __restrict__ a_d)
{
    int gw = (blockIdx.x * blockDim.x + threadIdx.x) >> 5;
    int lane = threadIdx.x & 31;
    if (gw >= N_NODES) return;
    const float* row = g_h + (size_t)gw * CH;
    float c0 = 0.f, c1 = 0.f;
    for (int k = lane; k < CH; k += 32) {
        float v = row[k];
        c0 = fmaf(v, W[2 * k + 0], c0);
        c1 = fmaf(v, W[2 * k + 1], c1);
    }
#pragma unroll
    for (int o = 16; o; o >>= 1) {
        c0 += __shfl_down_sync(0xffffffffu, c0, o);
        c1 += __shfl_down_sync(0xffffffffu, c1, o);
    }
    if (lane == 0) {
        g_hw[2 * gw + 0] = c0;
        g_hw[2 * gw + 1] = c1;
        g_as[gw] = c0 * a_s[0] + c1 * a_s[1];
        g_ad[gw] = c0 * a_d[0] + c1 * a_d[1];
    }
}

// ---------------- softmax-attention aggregation (block per dst node) ----------
__device__ __forceinline__ float leaky(float x) {
    return x > 0.f ? x : NEG_SLOPE * x;
}

__global__ __launch_bounds__(128) void k_aggregate(
    const float* __restrict__ bias, float* __restrict__ out_ext,
    int use_ext_out, int Co, int do_relu)
{
    int i = blockIdx.x;
    int t = threadIdx.x;           // 128 threads
    int s0 = g_off[i], s1 = g_off[i + 1];
    float adi = g_ad[i];
    __shared__ float red[128];

    // pass 1: max logit
    float mx = -1e30f;
    for (int j = s0 + t; j < s1; j += 128)
        mx = fmaxf(mx, leaky(g_as[g_srcs[j]] + adi));
    red[t] = mx; __syncthreads();
    for (int o = 64; o; o >>= 1) {
        if (t < o) red[t] = fmaxf(red[t], red[t + o]);
        __syncthreads();
    }
    mx = red[0]; __syncthreads();

    // pass 2: sum of exp
    float sm = 0.f;
    for (int j = s0 + t; j < s1; j += 128)
        sm += __expf(leaky(g_as[g_srcs[j]] + adi) - mx);
    red[t] = sm; __syncthreads();
    for (int o = 64; o; o >>= 1) {
        if (t < o) red[t] += red[t + o];
        __syncthreads();
    }
    float inv = 1.f / red[0];

    // pass 3: weighted gather-accumulate (whole block walks the edge list,
    // each thread owns up to 5 columns -> fully coalesced row reads)
    float acc[5] = {0.f, 0.f, 0.f, 0.f, 0.f};
    for (int j = s0; j < s1; j++) {
        int s = g_srcs[j];
        float w = __expf(leaky(g_as[s] + adi) - mx) * inv;
        const float* row = g_hw + (size_t)s * Co;
#pragma unroll
        for (int k = 0; k < 5; k++) {
            int c = t + k * 128;
            if (c < Co) acc[k] = fmaf(w, row[c], acc[k]);
        }
    }
    float* out = use_ext_out ? out_ext : (float*)g_h;
#pragma unroll
    for (int k = 0; k < 5; k++) {
        int c = t + k * 128;
        if (c < Co) {
            float v = acc[k] + bias[c];
            out[(size_t)i * Co + c] = do_relu ? fmaxf(v, 0.f) : v;
        }
    }
}

// ---------------- launch (kernel launches ONLY; no other CUDA API) ------------
extern "C" void kernel_launch(void* const* d_in, const int* in_sizes, int n_in,
                              void* d_out, int out_size)
{
    const float* x  = (const float*)d_in[0];
    const void*  ei = d_in[1];
    const float* W[5]  = {(const float*)d_in[2],  (const float*)d_in[6],
                          (const float*)d_in[10], (const float*)d_in[14],
                          (const float*)d_in[18]};
    const float* As[5] = {(const float*)d_in[3],  (const float*)d_in[7],
                          (const float*)d_in[11], (const float*)d_in[15],
                          (const float*)d_in[19]};
    const float* Ad[5] = {(const float*)d_in[4],  (const float*)d_in[8],
                          (const float*)d_in[12], (const float*)d_in[16],
                          (const float*)d_in[20]};
    const float* Bv[5] = {(const float*)d_in[5],  (const float*)d_in[9],
                          (const float*)d_in[13], (const float*)d_in[17],
                          (const float*)d_in[21]};

    int E  = in_sizes[1] / 2;     // 320000
    int EA = E + N_NODES;         // 340000

    // --- dtype detect + CSR build (topology identical across layers) ---
    k_detect<<<1, 256>>>((const int*)ei);
    k_zero <<<(N_NODES + 255) / 256, 256>>>();
    k_count<<<(EA + 255) / 256, 256>>>(ei, E, EA);
    k_scan <<<1, 1024>>>();
    k_copy <<<(N_NODES + 255) / 256, 256>>>();
    k_fill <<<(EA + 255) / 256, 256>>>(ei, E, EA);

    dim3 ggrid(CH / 64, (N_NODES + 63) / 64);  // (10, 313)
    int  awarps = (N_NODES * 32 + 255) / 256;  // 2500 blocks of 256

    // --- layer 1 (Ci=128) ---
    gemm64<<<ggrid, 256>>>(x, 1, W[0], N_NODES, CIN);
    k_alphas<<<awarps, 256>>>(As[0], Ad[0]);
    k_aggregate<<<N_NODES, 128>>>(Bv[0], nullptr, 0, CH, 1);

    // --- layers 2..4 (Ci=640) ---
    for (int l = 1; l < 4; l++) {
        gemm64<<<ggrid, 256>>>(nullptr, 0, W[l], N_NODES, CH);
        k_alphas<<<awarps, 256>>>(As[l], Ad[l]);
        k_aggregate<<<N_NODES, 128>>>(Bv[l], nullptr, 0, CH, 1);
    }

    // --- layer 5 (Co=2, no relu) ---
    k_layer5<<<awarps, 256>>>(W[4], As[4], Ad[4]);
    k_aggregate<<<N_NODES, 128>>>(Bv[4], (float*)d_out, 1, COUT, 0);
}

// round 6
// speedup vs baseline: 1.4312x; 1.4312x over previous
#include <cuda_runtime.h>
#include <cuda_bf16.h>
#include <math.h>
#include <mma.h>

using namespace nvcuda;

// Problem constants (fixed by the dataset)
#define N_NODES 20000
#define CIN     128
#define CH      640
#define COUT    2
#define E_IN    320000
#define EA_MAX  (E_IN + N_NODES)   // edges + self loops = 340000
#define NEG_SLOPE 0.2f
#define M_PAD   (N_NODES + 128)    // GEMM tiles may overrun M; pad activations

// ---------------- scratch (device globals; referenced ONLY from device code) ----
__device__ float g_h [M_PAD * CH];     // layer input/output activations (padded)
__device__ float g_hw[M_PAD * CH];     // hW = h @ W (padded)
__device__ float g_as[N_NODES];        // per-node alpha_src = hW . a_src
__device__ float g_ad[N_NODES];        // per-node alpha_dst = hW . a_dst
__device__ int   g_off [N_NODES + 1];  // CSR offsets by dst
__device__ int   g_fill[N_NODES];      // degree counter / fill pointer
__device__ int   g_srcs[EA_MAX];       // src node per CSR slot
__device__ int   g_is64;               // 1 if edge_index is int64, 0 if int32

// ---------------- edge_index dtype detection ----------------
__global__ void k_detect(const int* __restrict__ ei32) {
    __shared__ int nz;
    if (threadIdx.x == 0) nz = 0;
    __syncthreads();
    for (int i = threadIdx.x; i < 1024; i += blockDim.x)
        if (ei32[2 * i + 1] != 0) nz = 1;
    __syncthreads();
    if (threadIdx.x == 0) g_is64 = (nz == 0) ? 1 : 0;
}

__device__ __forceinline__ int edge_at(const void* ei, int idx) {
    return g_is64 ? (int)((const long long*)ei)[idx]
                  : ((const int*)ei)[idx];
}

// ---------------- CSR build (dst-sorted edge list) ----------------
__global__ void k_zero() {
    int i = blockIdx.x * blockDim.x + threadIdx.x;
    if (i < N_NODES) g_fill[i] = 0;
}

__global__ void k_count(const void* __restrict__ ei, int E, int EA) {
    int j = blockIdx.x * blockDim.x + threadIdx.x;
    if (j >= EA) return;
    int dst = (j < E) ? edge_at(ei, E + j) : (j - E);
    if (dst < 0 || dst >= N_NODES) return;
    atomicAdd(&g_fill[dst], 1);
}

__global__ void k_scan() {   // exclusive scan of g_fill -> g_off, single block of 1024
    __shared__ int part[1024];
    const int n = N_NODES;
    int t = threadIdx.x;
    const int chunk = (n + 1023) / 1024;
    int base = t * chunk;
    int s = 0;
    for (int i = 0; i < chunk; i++) {
        int idx = base + i;
        if (idx < n) s += g_fill[idx];
    }
    part[t] = s;
    __syncthreads();
    for (int o = 1; o < 1024; o <<= 1) {
        int v = (t >= o) ? part[t - o] : 0;
        __syncthreads();
        part[t] += v;
        __syncthreads();
    }
    int run = (t == 0) ? 0 : part[t - 1];
    for (int i = 0; i < chunk; i++) {
        int idx = base + i;
        if (idx < n) { int d = g_fill[idx]; g_off[idx] = run; run += d; }
    }
    if (t == 1023) g_off[n] = part[1023];
}

__global__ void k_copy() {
    int i = blockIdx.x * blockDim.x + threadIdx.x;
    if (i < N_NODES) g_fill[i] = g_off[i];
}

__global__ void k_fill(const void* __restrict__ ei, int E, int EA) {
    int j = blockIdx.x * blockDim.x + threadIdx.x;
    if (j >= EA) return;
    int src = (j < E) ? edge_at(ei, j)     : (j - E);
    int dst = (j < E) ? edge_at(ei, E + j) : (j - E);
    if (dst < 0 || dst >= N_NODES) return;
    if (src < 0 || src >= N_NODES) src = 0;
    int pos = atomicAdd(&g_fill[dst], 1);
    if (pos >= 0 && pos < EA_MAX) g_srcs[pos] = src;
}

// ---------------- bf16x3 split-precision tensor GEMM ----------------
// g_hw[M,CH] = A[M,K] @ B[K,CH]  with fp32-level accuracy:
//   v = hi + lo (hi = bf16(v), lo = bf16(v - hi));  C ~= Ah*Bh + Ah*Bl + Al*Bh
// BM=128, BN=64, BK=32, 256 threads (8 warps: 4m x 2n), warp tile 32x32,
// wmma m16n16k16 bf16 with fp32 accumulators.
#define BM 128
#define BN 64
#define BK 32
#define LDA 40   // BK + 8 bf16 pad
#define LDB 72   // BN + 8 bf16 pad

__global__ __launch_bounds__(256) void gemm_b3(
    const float* __restrict__ Aext, int use_ext,
    const float* __restrict__ B, int M, int K)
{
    const float* A = use_ext ? Aext : (const float*)g_h;
    __shared__ __align__(16) __nv_bfloat16 Ah[BM][LDA];
    __shared__ __align__(16) __nv_bfloat16 Al[BM][LDA];
    __shared__ __align__(16) __nv_bfloat16 Bh[BK][LDB];
    __shared__ __align__(16) __nv_bfloat16 Bl[BK][LDB];

    int t = threadIdx.x;
    int bm = blockIdx.y * BM, bn = blockIdx.x * BN;
    int warp = t >> 5;
    int wm = (warp & 3) * 32;   // warp m offset
    int wn = (warp >> 2) * 32;  // warp n offset

    wmma::fragment<wmma::accumulator, 16, 16, 16, float> acc[2][2];
#pragma unroll
    for (int i = 0; i < 2; i++)
#pragma unroll
        for (int j = 0; j < 2; j++)
            wmma::fill_fragment(acc[i][j], 0.0f);

    for (int k0 = 0; k0 < K; k0 += BK) {
        // stage A tile (128x32 fp32 -> hi/lo bf16); 1024 float4, 4/thread
#pragma unroll
        for (int i = 0; i < 4; i++) {
            int idx = t + i * 256;
            int row = idx >> 3;
            int c4  = (idx & 7) << 2;
            float4 v = make_float4(0.f, 0.f, 0.f, 0.f);
            if (bm + row < M)
                v = *(const float4*)(A + (size_t)(bm + row) * K + k0 + c4);
            float vv[4] = {v.x, v.y, v.z, v.w};
#pragma unroll
            for (int e = 0; e < 4; e++) {
                __nv_bfloat16 h = __float2bfloat16(vv[e]);
                Ah[row][c4 + e] = h;
                Al[row][c4 + e] = __float2bfloat16(vv[e] - __bfloat162float(h));
            }
        }
        // stage B tile (32x64 fp32 -> hi/lo bf16); 512 float4, 2/thread
#pragma unroll
        for (int i = 0; i < 2; i++) {
            int idx = t + i * 256;
            int row = idx >> 4;
            int c4  = (idx & 15) << 2;
            float4 v = *(const float4*)(B + (size_t)(k0 + row) * CH + bn + c4);
            float vv[4] = {v.x, v.y, v.z, v.w};
#pragma unroll
            for (int e = 0; e < 4; e++) {
                __nv_bfloat16 h = __float2bfloat16(vv[e]);
                Bh[row][c4 + e] = h;
                Bl[row][c4 + e] = __float2bfloat16(vv[e] - __bfloat162float(h));
            }
        }
        __syncthreads();

#pragma unroll
        for (int kk = 0; kk < BK; kk += 16) {
            wmma::fragment<wmma::matrix_a, 16, 16, 16, __nv_bfloat16, wmma::row_major> ah[2], al[2];
            wmma::fragment<wmma::matrix_b, 16, 16, 16, __nv_bfloat16, wmma::row_major> bh[2], bl[2];
#pragma unroll
            for (int i = 0; i < 2; i++) {
                wmma::load_matrix_sync(ah[i], &Ah[wm + i * 16][kk], LDA);
                wmma::load_matrix_sync(al[i], &Al[wm + i * 16][kk], LDA);
            }
#pragma unroll
            for (int j = 0; j < 2; j++) {
                wmma::load_matrix_sync(bh[j], &Bh[kk][wn + j * 16], LDB);
                wmma::load_matrix_sync(bl[j], &Bl[kk][wn + j * 16], LDB);
            }
#pragma unroll
            for (int i = 0; i < 2; i++)
#pragma unroll
                for (int j = 0; j < 2; j++) {
                    wmma::mma_sync(acc[i][j], ah[i], bh[j], acc[i][j]);
                    wmma::mma_sync(acc[i][j], ah[i], bl[j], acc[i][j]);
                    wmma::mma_sync(acc[i][j], al[i], bh[j], acc[i][j]);
                }
        }
        __syncthreads();
    }

    // store (g_hw is padded; rows >= M are scratch)
#pragma unroll
    for (int i = 0; i < 2; i++)
#pragma unroll
        for (int j = 0; j < 2; j++)
            wmma::store_matrix_sync(
                g_hw + (size_t)(bm + wm + i * 16) * CH + bn + wn + j * 16,
                acc[i][j], CH, wmma::mem_row_major);
}

// ---------------- per-node attention logits (warp per node, reads g_hw) -------
__global__ void k_alphas(const float* __restrict__ a_s,
                         const float* __restrict__ a_d)
{
    int gw = (blockIdx.x * blockDim.x + threadIdx.x) >> 5;
    int lane = threadIdx.x & 31;
    if (gw >= N_NODES) return;
    const float* row = g_hw + (size_t)gw * CH;
    float s = 0.f, d = 0.f;
    for (int c = lane; c < CH; c += 32) {
        float v = row[c];
        s = fmaf(v, a_s[c], s);
        d = fmaf(v, a_d[c], d);
    }
#pragma unroll
    for (int o = 16; o; o >>= 1) {
        s += __shfl_down_sync(0xffffffffu, s, o);
        d += __shfl_down_sync(0xffffffffu, d, o);
    }
    if (lane == 0) { g_as[gw] = s; g_ad[gw] = d; }
}

// ---------------- layer 5 projection + logits (warp per node, Co=2) -----------
__global__ void k_layer5(const float* __restrict__ W,
                         const float* __restrict__ a_s,
                         const float* __restrict__ a_d)
{
    int gw = (blockIdx.x * blockDim.x + threadIdx.x) >> 5;
    int lane = threadIdx.x & 31;
    if (gw >= N_NODES) return;
    const float* row = g_h + (size_t)gw * CH;
    float c0 = 0.f, c1 = 0.f;
    for (int k = lane; k < CH; k += 32) {
        float v = row[k];
        c0 = fmaf(v, W[2 * k + 0], c0);
        c1 = fmaf(v, W[2 * k + 1], c1);
    }
#pragma unroll
    for (int o = 16; o; o >>= 1) {
        c0 += __shfl_down_sync(0xffffffffu, c0, o);
        c1 += __shfl_down_sync(0xffffffffu, c1, o);
    }
    if (lane == 0) {
        g_hw[2 * gw + 0] = c0;
        g_hw[2 * gw + 1] = c1;
        g_as[gw] = c0 * a_s[0] + c1 * a_s[1];
        g_ad[gw] = c0 * a_d[0] + c1 * a_d[1];
    }
}

// ---------------- softmax-attention aggregation (block per dst node) ----------
__device__ __forceinline__ float leaky(float x) {
    return x > 0.f ? x : NEG_SLOPE * x;
}

__global__ __launch_bounds__(128) void k_aggregate(
    const float* __restrict__ bias, float* __restrict__ out_ext,
    int use_ext_out, int Co, int do_relu)
{
    int i = blockIdx.x;
    int t = threadIdx.x;           // 128 threads
    int s0 = g_off[i], s1 = g_off[i + 1];
    float adi = g_ad[i];
    __shared__ float red[128];
    __shared__ float sw[128];
    __shared__ int   ssrc[128];

    // pass 1: max logit
    float mx = -1e30f;
    for (int j = s0 + t; j < s1; j += 128)
        mx = fmaxf(mx, leaky(g_as[g_srcs[j]] + adi));
    red[t] = mx; __syncthreads();
    for (int o = 64; o; o >>= 1) {
        if (t < o) red[t] = fmaxf(red[t], red[t + o]);
        __syncthreads();
    }
    mx = red[0]; __syncthreads();

    // pass 2: sum of exp
    float sm = 0.f;
    for (int j = s0 + t; j < s1; j += 128)
        sm += __expf(leaky(g_as[g_srcs[j]] + adi) - mx);
    red[t] = sm; __syncthreads();
    for (int o = 64; o; o >>= 1) {
        if (t < o) red[t] += red[t + o];
        __syncthreads();
    }
    float inv = 1.f / red[0];
    __syncthreads();

    // pass 3: stage per-edge weights in shared (one exp per edge), then
    // all threads walk the chunk; each thread owns up to 5 columns.
    float acc[5] = {0.f, 0.f, 0.f, 0.f, 0.f};
    for (int base = s0; base < s1; base += 128) {
        int j = base + t;
        if (j < s1) {
            int s = g_srcs[j];
            ssrc[t] = s;
            sw[t]   = __expf(leaky(g_as[s] + adi) - mx) * inv;
        }
        __syncthreads();
        int cnt = min(128, s1 - base);
        for (int jj = 0; jj < cnt; jj++) {
            float w = sw[jj];
            const float* row = g_hw + (size_t)ssrc[jj] * Co;
#pragma unroll
            for (int k = 0; k < 5; k++) {
                int c = t + k * 128;
                if (c < Co) acc[k] = fmaf(w, row[c], acc[k]);
            }
        }
        __syncthreads();
    }
    float* out = use_ext_out ? out_ext : (float*)g_h;
#pragma unroll
    for (int k = 0; k < 5; k++) {
        int c = t + k * 128;
        if (c < Co) {
            float v = acc[k] + bias[c];
            out[(size_t)i * Co + c] = do_relu ? fmaxf(v, 0.f) : v;
        }
    }
}

// ---------------- launch (kernel launches ONLY; no other CUDA API) ------------
extern "C" void kernel_launch(void* const* d_in, const int* in_sizes, int n_in,
                              void* d_out, int out_size)
{
    const float* x  = (const float*)d_in[0];
    const void*  ei = d_in[1];
    const float* W[5]  = {(const float*)d_in[2],  (const float*)d_in[6],
                          (const float*)d_in[10], (const float*)d_in[14],
                          (const float*)d_in[18]};
    const float* As[5] = {(const float*)d_in[3],  (const float*)d_in[7],
                          (const float*)d_in[11], (const float*)d_in[15],
                          (const float*)d_in[19]};
    const float* Ad[5] = {(const float*)d_in[4],  (const float*)d_in[8],
                          (const float*)d_in[12], (const float*)d_in[16],
                          (const float*)d_in[20]};
    const float* Bv[5] = {(const float*)d_in[5],  (const float*)d_in[9],
                          (const float*)d_in[13], (const float*)d_in[17],
                          (const float*)d_in[21]};

    int E  = in_sizes[1] / 2;     // 320000
    int EA = E + N_NODES;         // 340000

    // --- dtype detect + CSR build (topology identical across layers) ---
    k_detect<<<1, 256>>>((const int*)ei);
    k_zero <<<(N_NODES + 255) / 256, 256>>>();
    k_count<<<(EA + 255) / 256, 256>>>(ei, E, EA);
    k_scan <<<1, 1024>>>();
    k_copy <<<(N_NODES + 255) / 256, 256>>>();
    k_fill <<<(EA + 255) / 256, 256>>>(ei, E, EA);

    dim3 ggrid(CH / BN, (N_NODES + BM - 1) / BM);  // (10, 157)
    int  awarps = (N_NODES * 32 + 255) / 256;      // 2500 blocks of 256

    // --- layer 1 (Ci=128) ---
    gemm_b3<<<ggrid, 256>>>(x, 1, W[0], N_NODES, CIN);
    k_alphas<<<awarps, 256>>>(As[0], Ad[0]);
    k_aggregate<<<N_NODES, 128>>>(Bv[0], nullptr, 0, CH, 1);

    // --- layers 2..4 (Ci=640) ---
    for (int l = 1; l < 4; l++) {
        gemm_b3<<<ggrid, 256>>>(nullptr, 0, W[l], N_NODES, CH);
        k_alphas<<<awarps, 256>>>(As[l], Ad[l]);
        k_aggregate<<<N_NODES, 128>>>(Bv[l], nullptr, 0, CH, 1);
    }

    // --- layer 5 (Co=2, no relu) ---
    k_layer5<<<awarps, 256>>>(W[4], As[4], Ad[4]);
    k_aggregate<<<N_NODES, 128>>>(Bv[4], (float*)d_out, 1, COUT, 0);
}